// round 6
// baseline (speedup 1.0000x reference)
#include <cuda_runtime.h>
#include <cuda_fp16.h>
#include <cuda.h>
#include <math.h>
#include <stdint.h>

// ---------------- problem constants ----------------
#define T_STEPS 20
#define B_DIM   16384
#define P_DIM   256
#define H_DIM   512
#define S_DIM   512
#define C_DIM   128
#define SC_DIM  640
#define TAUF    0.25f
#define OMTF    0.75f

// ---------------- shared GEMM tile config ----------------
#define BM 128
#define BN 128
#define BK 64
#define NSTAGE 3
#define A_BYTES (BM * BK * 2)                 // 16384
#define B_BYTES (BN * BK * 2)                 // 16384
#define STAGE_BYTES (A_BYTES + B_BYTES)       // 32768
#define SMEM_TOTAL (2048 + NSTAGE * STAGE_BYTES)      // TMA GEMM (U)
#define OFF_FULL(s)  ((s) * 8)

// gemm_x (fp32-A GEMM for Z): 2 fp16 A stages + 3 TMA B stages
#define SMEMX_TOTAL (2048 + 2 * A_BYTES + NSTAGE * B_BYTES)   // 83968

// recurrent chain kernel: full A row-block in smem + 3-stage B ring
#define R_NK    (SC_DIM / BK)                 // 10
#define R_NC    (SC_DIM / BN)                 // 5
#define RA_BYTES (R_NK * A_BYTES)             // 163840
#define SMEMR_TOTAL (1024 + RA_BYTES + NSTAGE * B_BYTES)      // 214016

// ---------------- device scratch (static; no runtime alloc) ----------------
__device__ __align__(256) __half g_zbuf[(size_t)T_STEPS * B_DIM * H_DIM];
__device__ __align__(256) __half g_ubuf[(size_t)T_STEPS * B_DIM * S_DIM];
__device__ __align__(256) __half g_act0[(size_t)B_DIM * SC_DIM];
__device__ __align__(256) __half g_act1[(size_t)B_DIM * SC_DIM];
__device__ __align__(256) float  g_in  [(size_t)B_DIM * SC_DIM];
__device__ __align__(256) __half g_wphT [H_DIM * P_DIM];
__device__ __align__(256) __half g_whsT [S_DIM * H_DIM];
__device__ __align__(256) __half g_wbigT[SC_DIM * SC_DIM];

// ---------------- PTX helpers ----------------
__device__ __forceinline__ uint32_t smem_u32(const void* p) {
    uint32_t a;
    asm("{ .reg .u64 t; cvta.to.shared.u64 t, %1; cvt.u32.u64 %0, t; }" : "=r"(a) : "l"(p));
    return a;
}
__device__ __forceinline__ void mbar_init(uint32_t m, uint32_t cnt) {
    asm volatile("mbarrier.init.shared.b64 [%0], %1;" :: "r"(m), "r"(cnt) : "memory");
}
__device__ __forceinline__ void mbar_expect_tx(uint32_t m, uint32_t bytes) {
    asm volatile("mbarrier.arrive.expect_tx.shared.b64 _, [%0], %1;" :: "r"(m), "r"(bytes) : "memory");
}
__device__ __forceinline__ void mbar_wait(uint32_t m, uint32_t parity) {
    asm volatile(
        "{\n\t.reg .pred P;\n\t"
        "WL_%=:\n\t"
        "mbarrier.try_wait.parity.acquire.cta.shared::cta.b64 P, [%0], %1, 0x989680;\n\t"
        "@P bra.uni WD_%=;\n\t"
        "bra.uni WL_%=;\n\t"
        "WD_%=:\n\t}"
        :: "r"(m), "r"(parity) : "memory");
}
__device__ __forceinline__ void tma2d(uint32_t dst, const CUtensorMap* map, int x, int y, uint32_t mbar) {
    asm volatile(
        "cp.async.bulk.tensor.2d.shared::cta.global.tile.mbarrier::complete_tx::bytes "
        "[%0], [%1, {%2, %3}], [%4];"
        :: "r"(dst), "l"(map), "r"(x), "r"(y), "r"(mbar) : "memory");
}
__device__ __forceinline__ void ldsm4(uint32_t* r, uint32_t addr) {
    asm volatile("ldmatrix.sync.aligned.m8n8.x4.shared.b16 {%0,%1,%2,%3}, [%4];"
                 : "=r"(r[0]), "=r"(r[1]), "=r"(r[2]), "=r"(r[3]) : "r"(addr));
}
__device__ __forceinline__ void mma16816(float* c, const uint32_t* a, uint32_t b0, uint32_t b1) {
    asm volatile(
        "mma.sync.aligned.m16n8k16.row.col.f32.f16.f16.f32 "
        "{%0,%1,%2,%3}, {%4,%5,%6,%7}, {%8,%9}, {%0,%1,%2,%3};"
        : "+f"(c[0]), "+f"(c[1]), "+f"(c[2]), "+f"(c[3])
        : "r"(a[0]), "r"(a[1]), "r"(a[2]), "r"(a[3]), "r"(b0), "r"(b1));
}
__device__ __forceinline__ void cpa16(uint32_t dst, const void* src) {
    asm volatile("cp.async.cg.shared.global [%0], [%1], 16;" :: "r"(dst), "l"(src));
}
__device__ __forceinline__ void cpa_commit() { asm volatile("cp.async.commit_group;" ::: "memory"); }
template<int N> __device__ __forceinline__ void cpa_wait() {
    asm volatile("cp.async.wait_group %0;" :: "n"(N) : "memory");
}
__device__ __forceinline__ float sigf(float x) { return 1.0f / (1.0f + __expf(-x)); }

// ============================================================================
// gemm_x: Z = X(fp32) @ WphT^T, A converted fp32->fp16 in-kernel (no conv pass)
// A: ldg float4 -> cvt -> STS into 2-stage fp16 ring.  B: TMA 3-stage ring.
// ============================================================================
__global__ void __launch_bounds__(256, 2)
gemm_x(const float* __restrict__ X,
       const __grid_constant__ CUtensorMap tma_b,
       __half* __restrict__ hout)
{
    extern __shared__ char smem[];
    const uint32_t sb = smem_u32(smem);
    const uint32_t stage0 = (sb + 64 + 1023) & ~1023u;
    const uint32_t aBase = stage0;                 // 2 x 16KB fp16 A stages
    const uint32_t bBase = stage0 + 2 * A_BYTES;   // 3 x 16KB TMA B stages
    const int tid  = threadIdx.x;
    const int lane = tid & 31;
    const int w    = tid >> 5;
    const int wm   = w & 3;
    const int wn   = w >> 2;
    const int m0 = blockIdx.y * BM;
    const int n0 = blockIdx.x * BN;
    const int nk = P_DIM / BK;   // 4

    if (tid == 0) {
        #pragma unroll
        for (int s = 0; s < NSTAGE; s++) mbar_init(sb + OFF_FULL(s), 1);
    }
    __syncthreads();
    if (tid == 0) {
        #pragma unroll
        for (int kc = 0; kc < NSTAGE; kc++) {
            mbar_expect_tx(sb + OFF_FULL(kc), B_BYTES);
            tma2d(bBase + kc * B_BYTES, &tma_b, kc * BK, n0, sb + OFF_FULL(kc));
        }
    }

    // A conversion mapping: tile = 128 rows x 64 f32 cols; 2048 float4 / 256 thr = 8 each
    int rI[8], cI[8];
    uint32_t sOff[8];
    #pragma unroll
    for (int q = 0; q < 8; q++) {
        int i = tid + q * 256;
        int r = i >> 4, c4 = i & 15;
        int c0 = c4 * 4;
        rI[q] = r; cI[q] = c0;
        sOff[q] = (uint32_t)r * 128 + (uint32_t)((((c0 >> 3) ^ (r & 7)) * 16) + (c0 & 7) * 2);
    }

    float4 xv[8];
    #pragma unroll
    for (int q = 0; q < 8; q++)
        xv[q] = __ldg((const float4*)(X + (size_t)(m0 + rI[q]) * P_DIM + cI[q]));

    const uint32_t xr   = (uint32_t)(lane & 7) * 16;
    const uint32_t koff = (uint32_t)(lane >> 4) * 16;
    uint32_t aRow[2], bRow[4];
    #pragma unroll
    for (int mi = 0; mi < 2; mi++)
        aRow[mi] = (uint32_t)(wm * 32 + mi * 16 + (lane & 15)) * 128;
    #pragma unroll
    for (int nq = 0; nq < 4; nq++)
        bRow[nq] = (uint32_t)(wn * 64 + nq * 16 + (lane & 15)) * 128;

    float acc[2][8][4];
    #pragma unroll
    for (int mi = 0; mi < 2; mi++)
        #pragma unroll
        for (int ni = 0; ni < 8; ni++)
            #pragma unroll
            for (int q = 0; q < 4; q++) acc[mi][ni][q] = 0.0f;

    for (int kc = 0; kc < nk; kc++) {
        const uint32_t stA = aBase + (kc & 1) * A_BYTES;
        #pragma unroll
        for (int q = 0; q < 8; q++) {
            *(__half2*)(uintptr_t)0;  // (no-op placeholder removed by compiler)
            uint32_t d = stA + sOff[q];
            __half2 h01 = __floats2half2_rn(xv[q].x, xv[q].y);
            __half2 h23 = __floats2half2_rn(xv[q].z, xv[q].w);
            asm volatile("st.shared.b32 [%0], %1;" :: "r"(d),     "r"(*(uint32_t*)&h01));
            asm volatile("st.shared.b32 [%0], %1;" :: "r"(d + 4), "r"(*(uint32_t*)&h23));
        }
        if (kc + 1 < nk) {
            #pragma unroll
            for (int q = 0; q < 8; q++)
                xv[q] = __ldg((const float4*)(X + (size_t)(m0 + rI[q]) * P_DIM + (kc + 1) * BK + cI[q]));
        }
        mbar_wait(sb + OFF_FULL(kc % NSTAGE), (uint32_t)((kc / NSTAGE) & 1));
        __syncthreads();   // A STS visible + B ready

        const uint32_t stB = bBase + (kc % NSTAGE) * B_BYTES;
        #pragma unroll
        for (int k16 = 0; k16 < 4; k16++) {
            const uint32_t kb = (uint32_t)k16 * 32 + koff;
            uint32_t af[2][4], bf[4][4];
            #pragma unroll
            for (int mi = 0; mi < 2; mi++)
                ldsm4(af[mi], stA + aRow[mi] + (kb ^ xr));
            #pragma unroll
            for (int nq = 0; nq < 4; nq++)
                ldsm4(bf[nq], stB + bRow[nq] + (kb ^ xr));
            #pragma unroll
            for (int mi = 0; mi < 2; mi++)
                #pragma unroll
                for (int nq = 0; nq < 4; nq++) {
                    mma16816(acc[mi][nq * 2 + 0], af[mi], bf[nq][0], bf[nq][2]);
                    mma16816(acc[mi][nq * 2 + 1], af[mi], bf[nq][1], bf[nq][3]);
                }
        }
        __syncthreads();
        if (tid == 0 && kc + NSTAGE < nk) {
            const int kn = kc + NSTAGE;
            mbar_expect_tx(sb + OFF_FULL(kn % NSTAGE), B_BYTES);
            tma2d(bBase + (kn % NSTAGE) * B_BYTES, &tma_b, kn * BK, n0, sb + OFF_FULL(kn % NSTAGE));
        }
    }

    const int rbase = lane >> 2;
    const int cpair = (lane & 3) * 2;
    #pragma unroll
    for (int mi = 0; mi < 2; mi++)
        #pragma unroll
        for (int h = 0; h < 2; h++) {
            const int m = m0 + wm * 32 + mi * 16 + rbase + h * 8;
            #pragma unroll
            for (int ni = 0; ni < 8; ni++) {
                const int n = n0 + wn * 64 + ni * 8 + cpair;
                *(__half2*)(hout + (size_t)m * H_DIM + n) =
                    __floats2half2_rn(acc[mi][ni][h * 2 + 0], acc[mi][ni][h * 2 + 1]);
            }
        }
}

// ============================================================================
// TMA-fed fp16 GEMM (used for U = a_hps @ WhsT^T + bias_s)
// ============================================================================
__global__ void __launch_bounds__(256, 2)
tc_gemm_u(const __grid_constant__ CUtensorMap tma_a,
          const __grid_constant__ CUtensorMap tma_b,
          int nk, const float* __restrict__ bias,
          __half* __restrict__ hout, int nld)
{
    extern __shared__ char smem[];
    const uint32_t sb = smem_u32(smem);
    const uint32_t stage0 = (sb + 64 + 1023) & ~1023u;
    const int tid  = threadIdx.x;
    const int lane = tid & 31;
    const int w    = tid >> 5;
    const int wm   = w & 3;
    const int wn   = w >> 2;
    const int m0 = blockIdx.y * BM;
    const int n0 = blockIdx.x * BN;

    if (tid == 0) {
        #pragma unroll
        for (int s = 0; s < NSTAGE; s++) mbar_init(sb + OFF_FULL(s), 1);
    }
    __syncthreads();
    if (tid == 0) {
        int pre = nk < NSTAGE ? nk : NSTAGE;
        for (int kc = 0; kc < pre; kc++) {
            uint32_t st = stage0 + kc * STAGE_BYTES;
            mbar_expect_tx(sb + OFF_FULL(kc), STAGE_BYTES);
            tma2d(st,           &tma_a, kc * BK, m0, sb + OFF_FULL(kc));
            tma2d(st + A_BYTES, &tma_b, kc * BK, n0, sb + OFF_FULL(kc));
        }
    }

    const uint32_t xr   = (uint32_t)(lane & 7) * 16;
    const uint32_t koff = (uint32_t)(lane >> 4) * 16;
    uint32_t aRow[2], bRow[4];
    #pragma unroll
    for (int mi = 0; mi < 2; mi++)
        aRow[mi] = (uint32_t)(wm * 32 + mi * 16 + (lane & 15)) * 128;
    #pragma unroll
    for (int nq = 0; nq < 4; nq++)
        bRow[nq] = (uint32_t)(wn * 64 + nq * 16 + (lane & 15)) * 128;

    float acc[2][8][4];
    #pragma unroll
    for (int mi = 0; mi < 2; mi++)
        #pragma unroll
        for (int ni = 0; ni < 8; ni++)
            #pragma unroll
            for (int q = 0; q < 4; q++) acc[mi][ni][q] = 0.0f;

    for (int kc = 0; kc < nk; kc++) {
        const int s = kc % NSTAGE;
        mbar_wait(sb + OFF_FULL(s), (uint32_t)((kc / NSTAGE) & 1));
        const uint32_t stA = stage0 + s * STAGE_BYTES;
        const uint32_t stB = stA + A_BYTES;
        #pragma unroll
        for (int k16 = 0; k16 < 4; k16++) {
            const uint32_t kb = (uint32_t)k16 * 32 + koff;
            uint32_t af[2][4], bf[4][4];
            #pragma unroll
            for (int mi = 0; mi < 2; mi++)
                ldsm4(af[mi], stA + aRow[mi] + (kb ^ xr));
            #pragma unroll
            for (int nq = 0; nq < 4; nq++)
                ldsm4(bf[nq], stB + bRow[nq] + (kb ^ xr));
            #pragma unroll
            for (int mi = 0; mi < 2; mi++)
                #pragma unroll
                for (int nq = 0; nq < 4; nq++) {
                    mma16816(acc[mi][nq * 2 + 0], af[mi], bf[nq][0], bf[nq][2]);
                    mma16816(acc[mi][nq * 2 + 1], af[mi], bf[nq][1], bf[nq][3]);
                }
        }
        __syncthreads();
        if (tid == 0 && kc + NSTAGE < nk) {
            const int kn = kc + NSTAGE;
            const int s2 = kn % NSTAGE;
            const uint32_t st = stage0 + s2 * STAGE_BYTES;
            mbar_expect_tx(sb + OFF_FULL(s2), STAGE_BYTES);
            tma2d(st,           &tma_a, kn * BK, m0, sb + OFF_FULL(s2));
            tma2d(st + A_BYTES, &tma_b, kn * BK, n0, sb + OFF_FULL(s2));
        }
    }

    const int rbase = lane >> 2;
    const int cpair = (lane & 3) * 2;
    #pragma unroll
    for (int mi = 0; mi < 2; mi++)
        #pragma unroll
        for (int h = 0; h < 2; h++) {
            const int m = m0 + wm * 32 + mi * 16 + rbase + h * 8;
            #pragma unroll
            for (int ni = 0; ni < 8; ni++) {
                const int n = n0 + wn * 64 + ni * 8 + cpair;
                *(__half2*)(hout + (size_t)m * nld + n) =
                    __floats2half2_rn(acc[mi][ni][h * 2 + 0] + bias[n],
                                      acc[mi][ni][h * 2 + 1] + bias[n + 1]);
            }
        }
}

// ============================================================================
// rec_chain: 128 independent persistent chains, one CTA per 128-row block.
// Full A (act, 128x640 fp16) in smem, reused by all 5 n-chunks per step.
// act ping-pong + fp32 carry live in L2 (.cg accesses). No cross-CTA sync.
// ============================================================================
__global__ void __launch_bounds__(256, 1)
rec_chain(const float* __restrict__ bias_css, float* __restrict__ out)
{
    extern __shared__ char smem[];
    const uint32_t sb = smem_u32(smem);
    const uint32_t A0 = (sb + 16 + 1023) & ~1023u;    // 10 x 16KB act tiles
    const uint32_t B0 = A0 + RA_BYTES;                // 3 x 16KB B ring
    const int tid  = threadIdx.x;
    const int lane = tid & 31;
    const int w    = tid >> 5;
    const int wm   = w & 3;
    const int wn   = w >> 2;
    const int m0 = blockIdx.x * BM;

    // cp.async dst mapping: 1024 16B-chunks per 16KB tile; 4 per thread
    uint32_t dstOff[4];
    int rIdx[4], cIdx[4];
    #pragma unroll
    for (int p = 0; p < 4; p++) {
        int i = tid + p * 256;
        int r = i >> 3, c = i & 7;
        rIdx[p] = r; cIdx[p] = c;
        dstOff[p] = (uint32_t)r * 128 + (uint32_t)((c ^ (r & 7)) * 16);
    }

    const uint32_t xr   = (uint32_t)(lane & 7) * 16;
    const uint32_t koff = (uint32_t)(lane >> 4) * 16;
    uint32_t aRow[2], bRow[4];
    #pragma unroll
    for (int mi = 0; mi < 2; mi++)
        aRow[mi] = (uint32_t)(wm * 32 + mi * 16 + (lane & 15)) * 128;
    #pragma unroll
    for (int nq = 0; nq < 4; nq++)
        bRow[nq] = (uint32_t)(wn * 64 + nq * 16 + (lane & 15)) * 128;

    const int rbase = lane >> 2;
    const int cpair = (lane & 3) * 2;

    #pragma unroll 1
    for (int t = 0; t < T_STEPS; t++) {
        const __half* Aact = (t & 1) ? g_act1 : g_act0;
        __half*       Aout = (t & 1) ? g_act0 : g_act1;
        const __half* U    = g_ubuf + (size_t)t * B_DIM * S_DIM;
        float* dptr = (t >= T_STEPS - 4)
                      ? out + (size_t)(t - (T_STEPS - 4)) * B_DIM * S_DIM
                      : nullptr;

        // load full act row-block into smem (one commit group)
        #pragma unroll 1
        for (int kc = 0; kc < R_NK; kc++) {
            #pragma unroll
            for (int p = 0; p < 4; p++)
                cpa16(A0 + kc * A_BYTES + dstOff[p],
                      Aact + (size_t)(m0 + rIdx[p]) * SC_DIM + kc * BK + cIdx[p] * 8);
        }
        cpa_commit();

        #pragma unroll 1
        for (int nc = 0; nc < R_NC; nc++) {
            const int n0 = nc * BN;
            // B ring prologue (3 commit groups)
            #pragma unroll
            for (int s = 0; s < NSTAGE; s++) {
                #pragma unroll
                for (int p = 0; p < 4; p++)
                    cpa16(B0 + s * B_BYTES + dstOff[p],
                          g_wbigT + (size_t)(n0 + rIdx[p]) * SC_DIM + s * BK + cIdx[p] * 8);
                cpa_commit();
            }

            float acc[2][8][4];
            #pragma unroll
            for (int mi = 0; mi < 2; mi++)
                #pragma unroll
                for (int ni = 0; ni < 8; ni++)
                    #pragma unroll
                    for (int q = 0; q < 4; q++) acc[mi][ni][q] = 0.0f;

            #pragma unroll 1
            for (int kc = 0; kc < R_NK; kc++) {
                if (kc <= R_NK - 3)      cpa_wait<NSTAGE - 1>();
                else if (kc == R_NK - 2) cpa_wait<1>();
                else                     cpa_wait<0>();
                __syncthreads();

                const uint32_t stA = A0 + kc * A_BYTES;
                const uint32_t stB = B0 + (kc % NSTAGE) * B_BYTES;
                #pragma unroll
                for (int k16 = 0; k16 < 4; k16++) {
                    const uint32_t kb = (uint32_t)k16 * 32 + koff;
                    uint32_t af[2][4], bf[4][4];
                    #pragma unroll
                    for (int mi = 0; mi < 2; mi++)
                        ldsm4(af[mi], stA + aRow[mi] + (kb ^ xr));
                    #pragma unroll
                    for (int nq = 0; nq < 4; nq++)
                        ldsm4(bf[nq], stB + bRow[nq] + (kb ^ xr));
                    #pragma unroll
                    for (int mi = 0; mi < 2; mi++)
                        #pragma unroll
                        for (int nq = 0; nq < 4; nq++) {
                            mma16816(acc[mi][nq * 2 + 0], af[mi], bf[nq][0], bf[nq][2]);
                            mma16816(acc[mi][nq * 2 + 1], af[mi], bf[nq][1], bf[nq][3]);
                        }
                }
                __syncthreads();
                if (kc + NSTAGE < R_NK) {
                    const int kn = kc + NSTAGE;
                    const uint32_t st = B0 + (kn % NSTAGE) * B_BYTES;
                    #pragma unroll
                    for (int p = 0; p < 4; p++)
                        cpa16(st + dstOff[p],
                              g_wbigT + (size_t)(n0 + rIdx[p]) * SC_DIM + kn * BK + cIdx[p] * 8);
                    cpa_commit();
                }
            }

            // fused leaky-integrator epilogue for this n-chunk
            const bool css = (n0 >= S_DIM);
            #pragma unroll
            for (int mi = 0; mi < 2; mi++)
                #pragma unroll
                for (int h = 0; h < 2; h++) {
                    const int mr = m0 + wm * 32 + mi * 16 + rbase + h * 8;
                    #pragma unroll
                    for (int ni = 0; ni < 8; ni++) {
                        const int n = n0 + wn * 64 + ni * 8 + cpair;
                        const float c0 = acc[mi][ni][h * 2 + 0];
                        const float c1 = acc[mi][ni][h * 2 + 1];
                        const size_t ib = (size_t)mr * SC_DIM + n;
                        float2 iv = __ldcg((const float2*)(g_in + ib));
                        float v0, v1;
                        if (!css) {
                            const __half2 uh = *(const __half2*)(U + (size_t)mr * S_DIM + n);
                            const float2 uf = __half22float2(uh);
                            v0 = TAUF * (c0 + uf.x) + OMTF * iv.x;
                            v1 = TAUF * (c1 + uf.y) + OMTF * iv.y;
                        } else {
                            v0 = TAUF * (c0 + bias_css[n - S_DIM])     + OMTF * iv.x;
                            v1 = TAUF * (c1 + bias_css[n - S_DIM + 1]) + OMTF * iv.y;
                        }
                        __stcg((float2*)(g_in + ib), make_float2(v0, v1));
                        const float a0 = sigf(v0), a1 = sigf(v1);
                        const __half2 ah = __floats2half2_rn(a0, a1);
                        __stcg((unsigned*)(Aout + ib), *(const unsigned*)&ah);
                        if (!css && dptr)
                            *(float2*)(dptr + (size_t)mr * S_DIM + n) = make_float2(a0, a1);
                    }
                }
        }
        __threadfence();      // act/carry stores visible before next step's cp.async
        __syncthreads();
    }
}

// ---------------- small helper kernels ----------------
__global__ void hps_scan(const float* __restrict__ bias_hps) {
    int idx = blockIdx.x * blockDim.x + threadIdx.x;
    if (idx >= B_DIM * H_DIM) return;
    float b = bias_hps[idx % H_DIM];
    float prev = 0.0f;
    #pragma unroll
    for (int t = 0; t < T_STEPS; t++) {
        size_t off = (size_t)t * (B_DIM * H_DIM) + idx;
        float z = __half2float(g_zbuf[off]);
        g_zbuf[off] = __float2half_rn(sigf(prev));
        prev = TAUF * (z + b) + OMTF * prev;
    }
}

__global__ void init_state() {
    int idx = blockIdx.x * blockDim.x + threadIdx.x;
    if (idx >= B_DIM * SC_DIM) return;
    g_in[idx] = 0.0f;
    g_act0[idx] = __float2half_rn(0.5f);
}

__global__ void prep_wph(const float* __restrict__ w) {
    int i = blockIdx.x * blockDim.x + threadIdx.x;
    if (i >= H_DIM * P_DIM) return;
    int n = i / P_DIM, k = i % P_DIM;
    g_wphT[i] = __float2half_rn(w[k * H_DIM + n]);
}
__global__ void prep_whs(const float* __restrict__ w) {
    int i = blockIdx.x * blockDim.x + threadIdx.x;
    if (i >= S_DIM * H_DIM) return;
    int n = i / H_DIM, k = i % H_DIM;
    g_whsT[i] = __float2half_rn(w[k * S_DIM + n]);
}
__global__ void prep_wbig(const float* __restrict__ w_ss,
                          const float* __restrict__ w_sc,
                          const float* __restrict__ w_cs) {
    int i = blockIdx.x * blockDim.x + threadIdx.x;
    if (i >= SC_DIM * SC_DIM) return;
    int n = i / SC_DIM, k = i % SC_DIM;
    float v;
    if (n < S_DIM) v = (k < S_DIM) ? w_ss[k * S_DIM + n] : w_cs[(k - S_DIM) * S_DIM + n];
    else           v = (k < S_DIM) ? w_sc[k * C_DIM + (n - S_DIM)] : 0.0f;
    g_wbigT[i] = __float2half_rn(v);
}

// ---------------- host side ----------------
typedef CUresult (*PFN_tmapEncode)(
    CUtensorMap*, CUtensorMapDataType, cuuint32_t, void*,
    const cuuint64_t*, const cuuint64_t*, const cuuint32_t*, const cuuint32_t*,
    CUtensorMapInterleave, CUtensorMapSwizzle, CUtensorMapL2promotion,
    CUtensorMapFloatOOBfill);

static void make_map2d(PFN_tmapEncode fn, CUtensorMap* m, void* ptr,
                       uint64_t K, uint64_t M) {
    cuuint64_t dims[2]    = {K, M};
    cuuint64_t strides[1] = {K * 2};
    cuuint32_t box[2]     = {BK, BM};
    cuuint32_t es[2]      = {1, 1};
    fn(m, CU_TENSOR_MAP_DATA_TYPE_FLOAT16, 2, ptr, dims, strides, box, es,
       CU_TENSOR_MAP_INTERLEAVE_NONE, CU_TENSOR_MAP_SWIZZLE_128B,
       CU_TENSOR_MAP_L2_PROMOTION_L2_128B, CU_TENSOR_MAP_FLOAT_OOB_FILL_NONE);
}

extern "C" void kernel_launch(void* const* d_in, const int* in_sizes, int n_in,
                              void* d_out, int out_size)
{
    const float* x     = (const float*)d_in[0];
    const float* w_ph  = (const float*)d_in[1];
    const float* w_hs  = (const float*)d_in[2];
    const float* w_ss  = (const float*)d_in[3];
    const float* w_sc  = (const float*)d_in[4];
    const float* w_cs  = (const float*)d_in[5];
    const float* b_hps = (const float*)d_in[6];
    const float* b_s   = (const float*)d_in[7];
    const float* b_css = (const float*)d_in[8];
    float* out = (float*)d_out;

    void *zbuf, *ubuf, *wphT, *whsT;
    cudaGetSymbolAddress(&zbuf, g_zbuf);
    cudaGetSymbolAddress(&ubuf, g_ubuf);
    cudaGetSymbolAddress(&wphT, g_wphT);
    cudaGetSymbolAddress(&whsT, g_whsT);

    PFN_tmapEncode encode = nullptr;
    cudaDriverEntryPointQueryResult qr;
    cudaGetDriverEntryPointByVersion("cuTensorMapEncodeTiled", (void**)&encode,
                                     12000, cudaEnableDefault, &qr);

    const uint64_t MB = (uint64_t)T_STEPS * B_DIM;   // 327680

    CUtensorMap m_wph, m_z, m_whs;
    make_map2d(encode, &m_wph, wphT, P_DIM, H_DIM);
    make_map2d(encode, &m_z,   zbuf, H_DIM, MB);
    make_map2d(encode, &m_whs, whsT, H_DIM, S_DIM);

    cudaFuncSetAttribute(gemm_x,    cudaFuncAttributeMaxDynamicSharedMemorySize, SMEMX_TOTAL);
    cudaFuncSetAttribute(tc_gemm_u, cudaFuncAttributeMaxDynamicSharedMemorySize, SMEM_TOTAL);
    cudaFuncSetAttribute(rec_chain, cudaFuncAttributeMaxDynamicSharedMemorySize, SMEMR_TOTAL);

    // 0) preps + state init
    prep_wph<<<(H_DIM * P_DIM + 255) / 256, 256>>>(w_ph);
    prep_whs<<<(S_DIM * H_DIM + 255) / 256, 256>>>(w_hs);
    prep_wbig<<<(SC_DIM * SC_DIM + 255) / 256, 256>>>(w_ss, w_sc, w_cs);
    init_state<<<(B_DIM * SC_DIM + 255) / 256, 256>>>();

    // 1) Z = X(fp32) @ WphT^T — conversion fused into the GEMM
    gemm_x<<<dim3(H_DIM / BN, (unsigned)(MB / BM)), 256, SMEMX_TOTAL>>>(
        x, m_wph, (__half*)zbuf);

    // 2) hps leaky scan (Z -> a_hps in place)
    hps_scan<<<(B_DIM * H_DIM) / 256, 256>>>(b_hps);

    // 3) U = a_hps @ WhsT^T + bias_s
    tc_gemm_u<<<dim3(S_DIM / BN, (unsigned)(MB / BM)), 256, SMEM_TOTAL>>>(
        m_z, m_whs, H_DIM / BK, b_s, (__half*)ubuf, S_DIM);

    // 4) 20 recurrent steps: 128 independent in-CTA chains, one launch
    rec_chain<<<B_DIM / BM, 256, SMEMR_TOTAL>>>(b_css, out);
}

// round 7
// speedup vs baseline: 1.4164x; 1.4164x over previous
#include <cuda_runtime.h>
#include <cuda_fp16.h>
#include <cuda.h>
#include <math.h>
#include <stdint.h>

// ---------------- problem constants ----------------
#define T_STEPS 20
#define B_DIM   16384
#define P_DIM   256
#define H_DIM   512
#define S_DIM   512
#define C_DIM   128
#define SC_DIM  640
#define TAUF    0.25f
#define OMTF    0.75f

// ---------------- GEMM tile config ----------------
#define BM 128
#define BN 128
#define BK 64
#define NSTAGE 3
#define A_BYTES (BM * BK * 2)                 // 16384
#define B_BYTES (BN * BK * 2)                 // 16384
#define STAGE_BYTES (A_BYTES + B_BYTES)       // 32768
#define SMEM_TOTAL (2048 + NSTAGE * STAGE_BYTES)   // 100352
#define OFF_FULL(s)  ((s) * 8)

// gemm_x: 2 fp16 A stages + 3 TMA B stages
#define SMEMX_TOTAL (2048 + 2 * A_BYTES + NSTAGE * B_BYTES)   // 83968

// recurrent persistent kernel
#define R_TILES_M   (B_DIM / BM)      // 128
#define R_TILES_N   (SC_DIM / BN)     // 5
#define R_TILES     (R_TILES_M * R_TILES_N)          // 640
#define R_TOTAL     (T_STEPS * R_TILES)              // 12800
#define R_NK        (SC_DIM / BK)     // 10
#define R_GRID      296               // 2 CTAs per SM

// ---------------- device scratch (static; no runtime alloc) ----------------
__device__ __align__(256) __half g_zbuf[(size_t)T_STEPS * B_DIM * H_DIM];
__device__ __align__(256) __half g_ubuf[(size_t)T_STEPS * B_DIM * S_DIM];
__device__ __align__(256) __half g_act0[(size_t)B_DIM * SC_DIM];
__device__ __align__(256) __half g_act1[(size_t)B_DIM * SC_DIM];
__device__ __align__(256) float  g_in  [(size_t)B_DIM * SC_DIM];
__device__ __align__(256) __half g_wphT [H_DIM * P_DIM];
__device__ __align__(256) __half g_whsT [S_DIM * H_DIM];
__device__ __align__(256) __half g_wbigT[SC_DIM * SC_DIM];
__device__ unsigned g_ready[T_STEPS * R_TILES_M];
__device__ unsigned g_counter;

// ---------------- PTX helpers ----------------
__device__ __forceinline__ uint32_t smem_u32(const void* p) {
    uint32_t a;
    asm("{ .reg .u64 t; cvta.to.shared.u64 t, %1; cvt.u32.u64 %0, t; }" : "=r"(a) : "l"(p));
    return a;
}
__device__ __forceinline__ void mbar_init(uint32_t m, uint32_t cnt) {
    asm volatile("mbarrier.init.shared.b64 [%0], %1;" :: "r"(m), "r"(cnt) : "memory");
}
__device__ __forceinline__ void mbar_expect_tx(uint32_t m, uint32_t bytes) {
    asm volatile("mbarrier.arrive.expect_tx.shared.b64 _, [%0], %1;" :: "r"(m), "r"(bytes) : "memory");
}
__device__ __forceinline__ void mbar_wait(uint32_t m, uint32_t parity) {
    asm volatile(
        "{\n\t.reg .pred P;\n\t"
        "WL_%=:\n\t"
        "mbarrier.try_wait.parity.acquire.cta.shared::cta.b64 P, [%0], %1, 0x989680;\n\t"
        "@P bra.uni WD_%=;\n\t"
        "bra.uni WL_%=;\n\t"
        "WD_%=:\n\t}"
        :: "r"(m), "r"(parity) : "memory");
}
__device__ __forceinline__ void tma2d(uint32_t dst, const CUtensorMap* map, int x, int y, uint32_t mbar) {
    asm volatile(
        "cp.async.bulk.tensor.2d.shared::cta.global.tile.mbarrier::complete_tx::bytes "
        "[%0], [%1, {%2, %3}], [%4];"
        :: "r"(dst), "l"(map), "r"(x), "r"(y), "r"(mbar) : "memory");
}
__device__ __forceinline__ void ldsm4(uint32_t* r, uint32_t addr) {
    asm volatile("ldmatrix.sync.aligned.m8n8.x4.shared.b16 {%0,%1,%2,%3}, [%4];"
                 : "=r"(r[0]), "=r"(r[1]), "=r"(r[2]), "=r"(r[3]) : "r"(addr));
}
__device__ __forceinline__ void mma16816(float* c, const uint32_t* a, uint32_t b0, uint32_t b1) {
    asm volatile(
        "mma.sync.aligned.m16n8k16.row.col.f32.f16.f16.f32 "
        "{%0,%1,%2,%3}, {%4,%5,%6,%7}, {%8,%9}, {%0,%1,%2,%3};"
        : "+f"(c[0]), "+f"(c[1]), "+f"(c[2]), "+f"(c[3])
        : "r"(a[0]), "r"(a[1]), "r"(a[2]), "r"(a[3]), "r"(b0), "r"(b1));
}
__device__ __forceinline__ void cpa16(uint32_t dst, const void* src) {
    asm volatile("cp.async.cg.shared.global [%0], [%1], 16;" :: "r"(dst), "l"(src));
}
__device__ __forceinline__ void cpa_commit() { asm volatile("cp.async.commit_group;" ::: "memory"); }
template<int N> __device__ __forceinline__ void cpa_wait() {
    asm volatile("cp.async.wait_group %0;" :: "n"(N) : "memory");
}
__device__ __forceinline__ float sigf(float x) { return 1.0f / (1.0f + __expf(-x)); }

// ============================================================================
// gemm_x: Z = X(fp32) @ WphT^T, fp32->fp16 conversion fused into A path.
// A: ldg float4 -> cvt -> STS (2-stage fp16 ring).  B: TMA 3-stage ring.
// ============================================================================
__global__ void __launch_bounds__(256, 2)
gemm_x(const float* __restrict__ X,
       const __grid_constant__ CUtensorMap tma_b,
       __half* __restrict__ hout)
{
    extern __shared__ char smem[];
    const uint32_t sb = smem_u32(smem);
    const uint32_t stage0 = (sb + 64 + 1023) & ~1023u;
    const uint32_t aBase = stage0;
    const uint32_t bBase = stage0 + 2 * A_BYTES;
    const int tid  = threadIdx.x;
    const int lane = tid & 31;
    const int w    = tid >> 5;
    const int wm   = w & 3;
    const int wn   = w >> 2;
    const int m0 = blockIdx.y * BM;
    const int n0 = blockIdx.x * BN;
    const int nk = P_DIM / BK;   // 4

    if (tid == 0) {
        #pragma unroll
        for (int s = 0; s < NSTAGE; s++) mbar_init(sb + OFF_FULL(s), 1);
    }
    __syncthreads();
    if (tid == 0) {
        #pragma unroll
        for (int kc = 0; kc < NSTAGE; kc++) {
            mbar_expect_tx(sb + OFF_FULL(kc), B_BYTES);
            tma2d(bBase + kc * B_BYTES, &tma_b, kc * BK, n0, sb + OFF_FULL(kc));
        }
    }

    int rI[8], cI[8];
    uint32_t sOff[8];
    #pragma unroll
    for (int q = 0; q < 8; q++) {
        int i = tid + q * 256;
        int r = i >> 4, c4 = i & 15;
        int c0 = c4 * 4;
        rI[q] = r; cI[q] = c0;
        sOff[q] = (uint32_t)r * 128 + (uint32_t)((((c0 >> 3) ^ (r & 7)) * 16) + (c0 & 7) * 2);
    }

    float4 xv[8];
    #pragma unroll
    for (int q = 0; q < 8; q++)
        xv[q] = __ldg((const float4*)(X + (size_t)(m0 + rI[q]) * P_DIM + cI[q]));

    const uint32_t xr   = (uint32_t)(lane & 7) * 16;
    const uint32_t koff = (uint32_t)(lane >> 4) * 16;
    uint32_t aRow[2], bRow[4];
    #pragma unroll
    for (int mi = 0; mi < 2; mi++)
        aRow[mi] = (uint32_t)(wm * 32 + mi * 16 + (lane & 15)) * 128;
    #pragma unroll
    for (int nq = 0; nq < 4; nq++)
        bRow[nq] = (uint32_t)(wn * 64 + nq * 16 + (lane & 15)) * 128;

    float acc[2][8][4];
    #pragma unroll
    for (int mi = 0; mi < 2; mi++)
        #pragma unroll
        for (int ni = 0; ni < 8; ni++)
            #pragma unroll
            for (int q = 0; q < 4; q++) acc[mi][ni][q] = 0.0f;

    for (int kc = 0; kc < nk; kc++) {
        const uint32_t stA = aBase + (kc & 1) * A_BYTES;
        #pragma unroll
        for (int q = 0; q < 8; q++) {
            uint32_t d = stA + sOff[q];
            __half2 h01 = __floats2half2_rn(xv[q].x, xv[q].y);
            __half2 h23 = __floats2half2_rn(xv[q].z, xv[q].w);
            asm volatile("st.shared.b32 [%0], %1;" :: "r"(d),     "r"(*(uint32_t*)&h01));
            asm volatile("st.shared.b32 [%0], %1;" :: "r"(d + 4), "r"(*(uint32_t*)&h23));
        }
        if (kc + 1 < nk) {
            #pragma unroll
            for (int q = 0; q < 8; q++)
                xv[q] = __ldg((const float4*)(X + (size_t)(m0 + rI[q]) * P_DIM + (kc + 1) * BK + cI[q]));
        }
        mbar_wait(sb + OFF_FULL(kc % NSTAGE), (uint32_t)((kc / NSTAGE) & 1));
        __syncthreads();

        const uint32_t stB = bBase + (kc % NSTAGE) * B_BYTES;
        #pragma unroll
        for (int k16 = 0; k16 < 4; k16++) {
            const uint32_t kb = (uint32_t)k16 * 32 + koff;
            uint32_t af[2][4], bf[4][4];
            #pragma unroll
            for (int mi = 0; mi < 2; mi++)
                ldsm4(af[mi], stA + aRow[mi] + (kb ^ xr));
            #pragma unroll
            for (int nq = 0; nq < 4; nq++)
                ldsm4(bf[nq], stB + bRow[nq] + (kb ^ xr));
            #pragma unroll
            for (int mi = 0; mi < 2; mi++)
                #pragma unroll
                for (int nq = 0; nq < 4; nq++) {
                    mma16816(acc[mi][nq * 2 + 0], af[mi], bf[nq][0], bf[nq][2]);
                    mma16816(acc[mi][nq * 2 + 1], af[mi], bf[nq][1], bf[nq][3]);
                }
        }
        __syncthreads();
        if (tid == 0 && kc + NSTAGE < nk) {
            const int kn = kc + NSTAGE;
            mbar_expect_tx(sb + OFF_FULL(kn % NSTAGE), B_BYTES);
            tma2d(bBase + (kn % NSTAGE) * B_BYTES, &tma_b, kn * BK, n0, sb + OFF_FULL(kn % NSTAGE));
        }
    }

    const int rbase = lane >> 2;
    const int cpair = (lane & 3) * 2;
    #pragma unroll
    for (int mi = 0; mi < 2; mi++)
        #pragma unroll
        for (int h = 0; h < 2; h++) {
            const int m = m0 + wm * 32 + mi * 16 + rbase + h * 8;
            #pragma unroll
            for (int ni = 0; ni < 8; ni++) {
                const int n = n0 + wn * 64 + ni * 8 + cpair;
                *(__half2*)(hout + (size_t)m * H_DIM + n) =
                    __floats2half2_rn(acc[mi][ni][h * 2 + 0], acc[mi][ni][h * 2 + 1]);
            }
        }
}

// ============================================================================
// TMA-fed fp16 GEMM (U = a_hps @ WhsT^T + bias_s)
// ============================================================================
__global__ void __launch_bounds__(256, 2)
tc_gemm_u(const __grid_constant__ CUtensorMap tma_a,
          const __grid_constant__ CUtensorMap tma_b,
          int nk, const float* __restrict__ bias,
          __half* __restrict__ hout, int nld)
{
    extern __shared__ char smem[];
    const uint32_t sb = smem_u32(smem);
    const uint32_t stage0 = (sb + 64 + 1023) & ~1023u;
    const int tid  = threadIdx.x;
    const int lane = tid & 31;
    const int w    = tid >> 5;
    const int wm   = w & 3;
    const int wn   = w >> 2;
    const int m0 = blockIdx.y * BM;
    const int n0 = blockIdx.x * BN;

    if (tid == 0) {
        #pragma unroll
        for (int s = 0; s < NSTAGE; s++) mbar_init(sb + OFF_FULL(s), 1);
    }
    __syncthreads();
    if (tid == 0) {
        int pre = nk < NSTAGE ? nk : NSTAGE;
        for (int kc = 0; kc < pre; kc++) {
            uint32_t st = stage0 + kc * STAGE_BYTES;
            mbar_expect_tx(sb + OFF_FULL(kc), STAGE_BYTES);
            tma2d(st,           &tma_a, kc * BK, m0, sb + OFF_FULL(kc));
            tma2d(st + A_BYTES, &tma_b, kc * BK, n0, sb + OFF_FULL(kc));
        }
    }

    const uint32_t xr   = (uint32_t)(lane & 7) * 16;
    const uint32_t koff = (uint32_t)(lane >> 4) * 16;
    uint32_t aRow[2], bRow[4];
    #pragma unroll
    for (int mi = 0; mi < 2; mi++)
        aRow[mi] = (uint32_t)(wm * 32 + mi * 16 + (lane & 15)) * 128;
    #pragma unroll
    for (int nq = 0; nq < 4; nq++)
        bRow[nq] = (uint32_t)(wn * 64 + nq * 16 + (lane & 15)) * 128;

    float acc[2][8][4];
    #pragma unroll
    for (int mi = 0; mi < 2; mi++)
        #pragma unroll
        for (int ni = 0; ni < 8; ni++)
            #pragma unroll
            for (int q = 0; q < 4; q++) acc[mi][ni][q] = 0.0f;

    for (int kc = 0; kc < nk; kc++) {
        const int s = kc % NSTAGE;
        mbar_wait(sb + OFF_FULL(s), (uint32_t)((kc / NSTAGE) & 1));
        const uint32_t stA = stage0 + s * STAGE_BYTES;
        const uint32_t stB = stA + A_BYTES;
        #pragma unroll
        for (int k16 = 0; k16 < 4; k16++) {
            const uint32_t kb = (uint32_t)k16 * 32 + koff;
            uint32_t af[2][4], bf[4][4];
            #pragma unroll
            for (int mi = 0; mi < 2; mi++)
                ldsm4(af[mi], stA + aRow[mi] + (kb ^ xr));
            #pragma unroll
            for (int nq = 0; nq < 4; nq++)
                ldsm4(bf[nq], stB + bRow[nq] + (kb ^ xr));
            #pragma unroll
            for (int mi = 0; mi < 2; mi++)
                #pragma unroll
                for (int nq = 0; nq < 4; nq++) {
                    mma16816(acc[mi][nq * 2 + 0], af[mi], bf[nq][0], bf[nq][2]);
                    mma16816(acc[mi][nq * 2 + 1], af[mi], bf[nq][1], bf[nq][3]);
                }
        }
        __syncthreads();
        if (tid == 0 && kc + NSTAGE < nk) {
            const int kn = kc + NSTAGE;
            const int s2 = kn % NSTAGE;
            const uint32_t st = stage0 + s2 * STAGE_BYTES;
            mbar_expect_tx(sb + OFF_FULL(s2), STAGE_BYTES);
            tma2d(st,           &tma_a, kn * BK, m0, sb + OFF_FULL(s2));
            tma2d(st + A_BYTES, &tma_b, kn * BK, n0, sb + OFF_FULL(s2));
        }
    }

    const int rbase = lane >> 2;
    const int cpair = (lane & 3) * 2;
    #pragma unroll
    for (int mi = 0; mi < 2; mi++)
        #pragma unroll
        for (int h = 0; h < 2; h++) {
            const int m = m0 + wm * 32 + mi * 16 + rbase + h * 8;
            #pragma unroll
            for (int ni = 0; ni < 8; ni++) {
                const int n = n0 + wn * 64 + ni * 8 + cpair;
                *(__half2*)(hout + (size_t)m * nld + n) =
                    __floats2half2_rn(acc[mi][ni][h * 2 + 0] + bias[n],
                                      acc[mi][ni][h * 2 + 1] + bias[n + 1]);
            }
        }
}

// ============================================================================
// Persistent recurrent kernel (R5-proven): counter-scheduled (t,m,n) tiles,
// ready-flag gating, cp.async SW128 loads, fused leaky epilogue.
// ============================================================================
__global__ void __launch_bounds__(256, 2)
rec_persist(const float* __restrict__ bias_css, float* __restrict__ out)
{
    extern __shared__ char smem[];
    unsigned* sg = (unsigned*)smem;
    const uint32_t sb = smem_u32(smem);
    const uint32_t stage0 = (sb + 16 + 1023) & ~1023u;
    const int tid  = threadIdx.x;
    const int lane = tid & 31;
    const int w    = tid >> 5;
    const int wm   = w & 3;
    const int wn   = w >> 2;

    uint32_t dstOff[4];
    int rIdx[4], cIdx[4];
    #pragma unroll
    for (int p = 0; p < 4; p++) {
        int i = tid + p * 256;
        int r = i >> 3, c = i & 7;
        rIdx[p] = r; cIdx[p] = c;
        dstOff[p] = (uint32_t)r * 128 + (uint32_t)((c ^ (r & 7)) * 16);
    }

    const uint32_t xr   = (uint32_t)(lane & 7) * 16;
    const uint32_t koff = (uint32_t)(lane >> 4) * 16;
    uint32_t aRow[2], bRow[4];
    #pragma unroll
    for (int mi = 0; mi < 2; mi++)
        aRow[mi] = (uint32_t)(wm * 32 + mi * 16 + (lane & 15)) * 128;
    #pragma unroll
    for (int nq = 0; nq < 4; nq++)
        bRow[nq] = (uint32_t)(wn * 64 + nq * 16 + (lane & 15)) * 128;

    while (true) {
        if (tid == 0) sg[0] = atomicAdd(&g_counter, 1u);
        __syncthreads();
        const unsigned g = sg[0];
        if (g >= (unsigned)R_TOTAL) break;

        const int t  = (int)(g / R_TILES);
        const int rm = (int)(g % R_TILES);
        const int m  = rm / R_TILES_N;
        const int nn = rm % R_TILES_N;
        const int m0 = m * BM;
        const int n0 = nn * BN;

        if (t > 0) {
            if (tid == 0) {
                while (*(volatile unsigned*)&g_ready[(t - 1) * R_TILES_M + m] < (unsigned)R_TILES_N)
                    __nanosleep(64);
                __threadfence();
            }
        }
        __syncthreads();

        const __half* Aact = (t & 1) ? g_act1 : g_act0;
        __half*       Aout = (t & 1) ? g_act0 : g_act1;

        #pragma unroll
        for (int s = 0; s < NSTAGE; s++) {
            const uint32_t st = stage0 + s * STAGE_BYTES;
            #pragma unroll
            for (int p = 0; p < 4; p++)
                cpa16(st + dstOff[p],
                      Aact + (size_t)(m0 + rIdx[p]) * SC_DIM + s * BK + cIdx[p] * 8);
            #pragma unroll
            for (int p = 0; p < 4; p++)
                cpa16(st + A_BYTES + dstOff[p],
                      g_wbigT + (size_t)(n0 + rIdx[p]) * SC_DIM + s * BK + cIdx[p] * 8);
            cpa_commit();
        }

        float acc[2][8][4];
        #pragma unroll
        for (int mi = 0; mi < 2; mi++)
            #pragma unroll
            for (int ni = 0; ni < 8; ni++)
                #pragma unroll
                for (int q = 0; q < 4; q++) acc[mi][ni][q] = 0.0f;

        #pragma unroll 1
        for (int kc = 0; kc < R_NK; kc++) {
            if (kc <= R_NK - 3)      cpa_wait<NSTAGE - 1>();
            else if (kc == R_NK - 2) cpa_wait<1>();
            else                     cpa_wait<0>();
            __syncthreads();

            const int s = kc % NSTAGE;
            const uint32_t stA = stage0 + s * STAGE_BYTES;
            const uint32_t stB = stA + A_BYTES;

            #pragma unroll
            for (int k16 = 0; k16 < 4; k16++) {
                const uint32_t kb = (uint32_t)k16 * 32 + koff;
                uint32_t af[2][4], bf[4][4];
                #pragma unroll
                for (int mi = 0; mi < 2; mi++)
                    ldsm4(af[mi], stA + aRow[mi] + (kb ^ xr));
                #pragma unroll
                for (int nq = 0; nq < 4; nq++)
                    ldsm4(bf[nq], stB + bRow[nq] + (kb ^ xr));
                #pragma unroll
                for (int mi = 0; mi < 2; mi++)
                    #pragma unroll
                    for (int nq = 0; nq < 4; nq++) {
                        mma16816(acc[mi][nq * 2 + 0], af[mi], bf[nq][0], bf[nq][2]);
                        mma16816(acc[mi][nq * 2 + 1], af[mi], bf[nq][1], bf[nq][3]);
                    }
            }
            __syncthreads();
            if (kc + NSTAGE < R_NK) {
                const int kn = kc + NSTAGE;
                const uint32_t st = stage0 + (kn % NSTAGE) * STAGE_BYTES;
                #pragma unroll
                for (int p = 0; p < 4; p++)
                    cpa16(st + dstOff[p],
                          Aact + (size_t)(m0 + rIdx[p]) * SC_DIM + kn * BK + cIdx[p] * 8);
                #pragma unroll
                for (int p = 0; p < 4; p++)
                    cpa16(st + A_BYTES + dstOff[p],
                          g_wbigT + (size_t)(n0 + rIdx[p]) * SC_DIM + kn * BK + cIdx[p] * 8);
                cpa_commit();
            }
        }

        const bool css = (n0 >= S_DIM);
        const __half* U = g_ubuf + (size_t)t * B_DIM * S_DIM;
        float* dptr = (t >= T_STEPS - 4)
                      ? out + (size_t)(t - (T_STEPS - 4)) * B_DIM * S_DIM
                      : nullptr;
        const int rbase = lane >> 2;
        const int cpair = (lane & 3) * 2;

        #pragma unroll
        for (int mi = 0; mi < 2; mi++) {
            #pragma unroll
            for (int h = 0; h < 2; h++) {
                const int mr = m0 + wm * 32 + mi * 16 + rbase + h * 8;
                #pragma unroll
                for (int ni = 0; ni < 8; ni++) {
                    const int n = n0 + wn * 64 + ni * 8 + cpair;
                    const float c0 = acc[mi][ni][h * 2 + 0];
                    const float c1 = acc[mi][ni][h * 2 + 1];
                    const size_t ib = (size_t)mr * SC_DIM + n;
                    float2 iv = *(const float2*)(g_in + ib);
                    float v0, v1;
                    if (!css) {
                        const float2 uf = __half22float2(*(const __half2*)(U + (size_t)mr * S_DIM + n));
                        v0 = TAUF * (c0 + uf.x) + OMTF * iv.x;
                        v1 = TAUF * (c1 + uf.y) + OMTF * iv.y;
                    } else {
                        v0 = TAUF * (c0 + bias_css[n - S_DIM])     + OMTF * iv.x;
                        v1 = TAUF * (c1 + bias_css[n - S_DIM + 1]) + OMTF * iv.y;
                    }
                    *(float2*)(g_in + ib) = make_float2(v0, v1);
                    const float a0 = sigf(v0), a1 = sigf(v1);
                    *(__half2*)(Aout + ib) = __floats2half2_rn(a0, a1);
                    if (!css && dptr)
                        *(float2*)(dptr + (size_t)mr * S_DIM + n) = make_float2(a0, a1);
                }
            }
        }

        __threadfence();
        __syncthreads();
        if (tid == 0) atomicAdd(&g_ready[t * R_TILES_M + m], 1u);
    }
}

// ---------------- small helper kernels ----------------
__global__ void hps_scan(const float* __restrict__ bias_hps) {
    int idx = blockIdx.x * blockDim.x + threadIdx.x;
    if (idx >= B_DIM * H_DIM) return;
    float b = bias_hps[idx % H_DIM];
    float prev = 0.0f;
    #pragma unroll
    for (int t = 0; t < T_STEPS; t++) {
        size_t off = (size_t)t * (B_DIM * H_DIM) + idx;
        float z = __half2float(g_zbuf[off]);
        g_zbuf[off] = __float2half_rn(sigf(prev));
        prev = TAUF * (z + b) + OMTF * prev;
    }
}

__global__ void init_state() {
    int idx = blockIdx.x * blockDim.x + threadIdx.x;
    if (idx >= B_DIM * SC_DIM) return;
    g_in[idx] = 0.0f;
    g_act0[idx] = __float2half_rn(0.5f);
    if (idx < T_STEPS * R_TILES_M) g_ready[idx] = 0u;
    if (idx == 0) g_counter = 0u;
}

__global__ void prep_wph(const float* __restrict__ w) {
    int i = blockIdx.x * blockDim.x + threadIdx.x;
    if (i >= H_DIM * P_DIM) return;
    int n = i / P_DIM, k = i % P_DIM;
    g_wphT[i] = __float2half_rn(w[k * H_DIM + n]);
}
__global__ void prep_whs(const float* __restrict__ w) {
    int i = blockIdx.x * blockDim.x + threadIdx.x;
    if (i >= S_DIM * H_DIM) return;
    int n = i / H_DIM, k = i % H_DIM;
    g_whsT[i] = __float2half_rn(w[k * S_DIM + n]);
}
__global__ void prep_wbig(const float* __restrict__ w_ss,
                          const float* __restrict__ w_sc,
                          const float* __restrict__ w_cs) {
    int i = blockIdx.x * blockDim.x + threadIdx.x;
    if (i >= SC_DIM * SC_DIM) return;
    int n = i / SC_DIM, k = i % SC_DIM;
    float v;
    if (n < S_DIM) v = (k < S_DIM) ? w_ss[k * S_DIM + n] : w_cs[(k - S_DIM) * S_DIM + n];
    else           v = (k < S_DIM) ? w_sc[k * C_DIM + (n - S_DIM)] : 0.0f;
    g_wbigT[i] = __float2half_rn(v);
}

// ---------------- host side ----------------
typedef CUresult (*PFN_tmapEncode)(
    CUtensorMap*, CUtensorMapDataType, cuuint32_t, void*,
    const cuuint64_t*, const cuuint64_t*, const cuuint32_t*, const cuuint32_t*,
    CUtensorMapInterleave, CUtensorMapSwizzle, CUtensorMapL2promotion,
    CUtensorMapFloatOOBfill);

static void make_map2d(PFN_tmapEncode fn, CUtensorMap* m, void* ptr,
                       uint64_t K, uint64_t M) {
    cuuint64_t dims[2]    = {K, M};
    cuuint64_t strides[1] = {K * 2};
    cuuint32_t box[2]     = {BK, BM};
    cuuint32_t es[2]      = {1, 1};
    fn(m, CU_TENSOR_MAP_DATA_TYPE_FLOAT16, 2, ptr, dims, strides, box, es,
       CU_TENSOR_MAP_INTERLEAVE_NONE, CU_TENSOR_MAP_SWIZZLE_128B,
       CU_TENSOR_MAP_L2_PROMOTION_L2_128B, CU_TENSOR_MAP_FLOAT_OOB_FILL_NONE);
}

extern "C" void kernel_launch(void* const* d_in, const int* in_sizes, int n_in,
                              void* d_out, int out_size)
{
    const float* x     = (const float*)d_in[0];
    const float* w_ph  = (const float*)d_in[1];
    const float* w_hs  = (const float*)d_in[2];
    const float* w_ss  = (const float*)d_in[3];
    const float* w_sc  = (const float*)d_in[4];
    const float* w_cs  = (const float*)d_in[5];
    const float* b_hps = (const float*)d_in[6];
    const float* b_s   = (const float*)d_in[7];
    const float* b_css = (const float*)d_in[8];
    float* out = (float*)d_out;

    void *zbuf, *ubuf, *wphT, *whsT;
    cudaGetSymbolAddress(&zbuf, g_zbuf);
    cudaGetSymbolAddress(&ubuf, g_ubuf);
    cudaGetSymbolAddress(&wphT, g_wphT);
    cudaGetSymbolAddress(&whsT, g_whsT);

    PFN_tmapEncode encode = nullptr;
    cudaDriverEntryPointQueryResult qr;
    cudaGetDriverEntryPointByVersion("cuTensorMapEncodeTiled", (void**)&encode,
                                     12000, cudaEnableDefault, &qr);

    const uint64_t MB = (uint64_t)T_STEPS * B_DIM;   // 327680

    CUtensorMap m_wph, m_z, m_whs;
    make_map2d(encode, &m_wph, wphT, P_DIM, H_DIM);
    make_map2d(encode, &m_z,   zbuf, H_DIM, MB);
    make_map2d(encode, &m_whs, whsT, H_DIM, S_DIM);

    cudaFuncSetAttribute(gemm_x,      cudaFuncAttributeMaxDynamicSharedMemorySize, SMEMX_TOTAL);
    cudaFuncSetAttribute(tc_gemm_u,   cudaFuncAttributeMaxDynamicSharedMemorySize, SMEM_TOTAL);
    cudaFuncSetAttribute(rec_persist, cudaFuncAttributeMaxDynamicSharedMemorySize, SMEM_TOTAL);

    // 0) preps + state/flag init
    prep_wph<<<(H_DIM * P_DIM + 255) / 256, 256>>>(w_ph);
    prep_whs<<<(S_DIM * H_DIM + 255) / 256, 256>>>(w_hs);
    prep_wbig<<<(SC_DIM * SC_DIM + 255) / 256, 256>>>(w_ss, w_sc, w_cs);
    init_state<<<(B_DIM * SC_DIM + 255) / 256, 256>>>();

    // 1) Z = X(fp32) @ WphT^T — conversion fused into the GEMM (no conv_x pass)
    gemm_x<<<dim3(H_DIM / BN, (unsigned)(MB / BM)), 256, SMEMX_TOTAL>>>(
        x, m_wph, (__half*)zbuf);

    // 2) hps leaky scan (Z -> a_hps in place)
    hps_scan<<<(B_DIM * H_DIM) / 256, 256>>>(b_hps);

    // 3) U = a_hps @ WhsT^T + bias_s
    tc_gemm_u<<<dim3(S_DIM / BN, (unsigned)(MB / BM)), 256, SMEM_TOTAL>>>(
        m_z, m_whs, H_DIM / BK, b_s, (__half*)ubuf, S_DIM);

    // 4) all 20 recurrent steps in ONE persistent launch (R5 scheduler)
    rec_persist<<<R_GRID, 256, SMEM_TOTAL>>>(b_css, out);
}